// round 16
// baseline (speedup 1.0000x reference)
#include <cuda_runtime.h>
#include <cuda_bf16.h>
#include <cstdint>

#define B_      64
#define WVEC    50890
#define NTEST   10000
#define INPUT_  784
#define KPAD    800
#define NCHUNK  25
#define HIDDEN_ 64
#define OUT_    10
#define O1 50176
#define O2 50240
#define O3 50880
#define NTILE_  79    // ceil(10000/128)
#define PREPB   1024  // prep kernel blocks

__device__ double g_acc2;
__device__ float  g_l1part[PREPB];
__device__ __nv_bfloat16 g_imgs_bf[NTEST * KPAD];          // 16 MB (K zero-padded)
__device__ __nv_bfloat16 g_w1_bf[B_ * HIDDEN_ * KPAD];     // 6.6 MB

// ---------------- fused prep: conversions + loss1 partials ----------------
__global__ __launch_bounds__(256) void prep_k(const float* __restrict__ images,
                                              const float* __restrict__ w,
                                              const float* __restrict__ a,
                                              const float* __restrict__ t) {
    if (blockIdx.x == 0 && threadIdx.x == 0) g_acc2 = 0.0;
    const int gtid = blockIdx.x * blockDim.x + threadIdx.x;
    const int gstr = gridDim.x * blockDim.x;

    {
        const int total = NTEST * KPAD / 2;
        __nv_bfloat162* dst = (__nv_bfloat162*)g_imgs_bf;
        for (int i = gtid; i < total; i += gstr) {
            int p = i % (KPAD / 2), row = i / (KPAD / 2);
            int k = 2 * p;
            __nv_bfloat162 v;
            if (k < INPUT_) {
                float2 f = *(const float2*)(images + (size_t)row * INPUT_ + k);
                v = __floats2bfloat162_rn(f.x, f.y);
            } else {
                v = __floats2bfloat162_rn(0.f, 0.f);
            }
            dst[i] = v;
        }
    }
    {
        const int total = B_ * HIDDEN_ * KPAD / 2;
        __nv_bfloat162* dst = (__nv_bfloat162*)g_w1_bf;
        for (int i = gtid; i < total; i += gstr) {
            int p = i % (KPAD / 2), r = i / (KPAD / 2);
            int b = r >> 6, j = r & 63;
            int k = 2 * p;
            __nv_bfloat162 v;
            if (k < INPUT_) {
                float2 f = *(const float2*)(w + (size_t)b * WVEC + j * INPUT_ + k);
                v = __floats2bfloat162_rn(f.x, f.y);
            } else {
                v = __floats2bfloat162_rn(0.f, 0.f);
            }
            dst[i] = v;
        }
    }
    {
        const int total4 = (B_ * WVEC) / 4;
        float s = 0.f;
        for (int i = gtid; i < total4; i += gstr) {
            float4 x = ((const float4*)a)[i];
            float4 y = ((const float4*)t)[i];
            float d0 = x.x - y.x, d1 = x.y - y.y, d2 = x.z - y.z, d3 = x.w - y.w;
            s += d0 * d0 + d1 * d1 + d2 * d2 + d3 * d3;
        }
        #pragma unroll
        for (int off = 16; off; off >>= 1) s += __shfl_down_sync(0xffffffffu, s, off);
        __shared__ float ws[8];
        int lane = threadIdx.x & 31, wrp = threadIdx.x >> 5;
        if (lane == 0) ws[wrp] = s;
        __syncthreads();
        if (threadIdx.x == 0) {
            float tot = 0.f;
            #pragma unroll
            for (int i = 0; i < 8; i++) tot += ws[i];
            g_l1part[blockIdx.x] = tot;
        }
    }
}

__device__ __forceinline__ uint32_t smem_u32(const void* p) {
    uint32_t a;
    asm("{ .reg .u64 t; cvta.to.shared.u64 t, %1; cvt.u32.u64 %0, t; }" : "=r"(a) : "l"(p));
    return a;
}
#define CP16(dst, src) \
    asm volatile("cp.async.cg.shared.global [%0], [%1], 16;" :: "r"(dst), "l"(src))
#define CP_COMMIT() asm volatile("cp.async.commit_group;" ::: "memory")
#define CP_WAIT(n)  asm volatile("cp.async.wait_group %0;" :: "n"(n) : "memory")
#define LDSM_X4(r0, r1, r2, r3, addr) \
    asm volatile("ldmatrix.sync.aligned.m8n8.x4.shared.b16 {%0,%1,%2,%3}, [%4];" \
                 : "=r"(r0), "=r"(r1), "=r"(r2), "=r"(r3) : "r"(addr))

// ---- bf16 mma.sync MLP forward + CE (1 batch/CTA, 8 m-strips, 3 CTAs/SM) ----
// CTA: 256 thr, 8 warps, each warp 16 rows x 64 hidden. M=128, K=800, b=blockIdx.y.
#define TSTRIDE 40                       // bf16 elems per smem row (80 B)
#define A_BYTES (128 * TSTRIDE * 2)      // 10240
#define B_BYTES (64 * TSTRIDE * 2)       // 5120
#define STAGE_T (A_BYTES + B_BYTES)      // 15360

__global__ __launch_bounds__(256, 3) void mlp_ce_mma_k(const float* __restrict__ w,
                                                       const int* __restrict__ tar2) {
    const int b  = blockIdx.y;
    const int n0 = blockIdx.x * 128;

    __shared__ __nv_bfloat16 stages[2 * STAGE_T / 2];
    __shared__ float w2s[OUT_ * HIDDEN_];
    __shared__ float b1s[HIDDEN_];
    __shared__ float b2s[OUT_];
    __shared__ float warpsum[8];

    const int tid = threadIdx.x, wid = tid >> 5, lane = tid & 31;
    const int g = lane >> 2, t = lane & 3;

    // stage-2 weights (scalar loads: alignment-safe)
    const float* Wb = w + (size_t)b * WVEC;
    #pragma unroll 1
    for (int i = tid; i < OUT_ * HIDDEN_; i += 256) w2s[i] = Wb[O2 + i];
    if (tid < HIDDEN_) b1s[tid] = Wb[O1 + tid];
    if (tid < OUT_)    b2s[tid] = Wb[O3 + tid];

    float acc[8][4];
    #pragma unroll
    for (int nt = 0; nt < 8; nt++)
        #pragma unroll
        for (int r = 0; r < 4; r++) acc[nt][r] = 0.f;

    const __nv_bfloat16* Ab = g_imgs_bf;
    const __nv_bfloat16* Bb = g_w1_bf + (size_t)b * HIDDEN_ * KPAD;

    // cp.async mapping:
    //  A: 2 threads/row (128 rows), each half copies 2x16B
    //  B: 4 threads/row (64 rows), each copies 1x16B
    const int rowA = tid >> 1, eA = (tid & 1) * 16;
    const int rowB = tid >> 2, qB = tid & 3;
    int gnA = n0 + rowA; if (gnA > NTEST - 1) gnA = NTEST - 1;
    const __nv_bfloat16* srcA = Ab + (size_t)gnA * KPAD + eA;
    const __nv_bfloat16* srcB = Bb + (size_t)rowB * KPAD + qB * 8;
    const uint32_t stU = smem_u32(stages);
    const uint32_t dstA = stU + rowA * (TSTRIDE * 2) + eA * 2;
    const uint32_t dstB = stU + A_BYTES + rowB * (TSTRIDE * 2) + qB * 16;

    // ldmatrix base addresses (stage 0, ks = 0)
    const uint32_t aAddr = stU + (((wid * 16 + (lane & 15)) * TSTRIDE) +
                                  ((lane >> 4) * 8)) * 2;
    uint32_t bAddr[4];
    #pragma unroll
    for (int ntp = 0; ntp < 4; ntp++)
        bAddr[ntp] = stU + A_BYTES +
                     (((ntp * 16 + ((lane >> 4) * 8) + (lane & 7)) * TSTRIDE) +
                      (((lane >> 3) & 1) * 8)) * 2;

    // prologue: stage 0
    CP16(dstA,      srcA);
    CP16(dstA + 16, srcA + 8);
    CP16(dstB,      srcB);
    CP_COMMIT();

    for (int c = 0; c < NCHUNK; c++) {
        CP_WAIT(0);
        // one barrier: publishes stage c AND proves all warps finished compute
        // of c-1 -> safe to overwrite stage (c+1)&1 below
        __syncthreads();
        if (c < NCHUNK - 1) {
            const uint32_t pOff = (uint32_t)((c + 1) & 1) * STAGE_T;
            const int k0 = (c + 1) * 32;
            CP16(dstA + pOff,      srcA + k0);
            CP16(dstA + pOff + 16, srcA + k0 + 8);
            CP16(dstB + pOff,      srcB + k0);
            CP_COMMIT();
        }
        const uint32_t stOff = (uint32_t)(c & 1) * STAGE_T;
        #pragma unroll
        for (int ks = 0; ks < 2; ks++) {
            const uint32_t ko = stOff + ks * 32;   // 16 bf16 = 32 B
            uint32_t a[4], bf[8][2];
            LDSM_X4(a[0], a[1], a[2], a[3], aAddr + ko);
            LDSM_X4(bf[0][0], bf[0][1], bf[1][0], bf[1][1], bAddr[0] + ko);
            LDSM_X4(bf[2][0], bf[2][1], bf[3][0], bf[3][1], bAddr[1] + ko);
            LDSM_X4(bf[4][0], bf[4][1], bf[5][0], bf[5][1], bAddr[2] + ko);
            LDSM_X4(bf[6][0], bf[6][1], bf[7][0], bf[7][1], bAddr[3] + ko);
            #pragma unroll
            for (int nt = 0; nt < 8; nt++)
                asm volatile(
                    "mma.sync.aligned.m16n8k16.row.col.f32.bf16.bf16.f32 "
                    "{%0,%1,%2,%3},{%4,%5,%6,%7},{%8,%9},{%0,%1,%2,%3};"
                    : "+f"(acc[nt][0]), "+f"(acc[nt][1]),
                      "+f"(acc[nt][2]), "+f"(acc[nt][3])
                    : "r"(a[0]), "r"(a[1]), "r"(a[2]), "r"(a[3]),
                      "r"(bf[nt][0]), "r"(bf[nt][1]));
        }
    }

    // ---- stage 2 straight from fragments ----
    // thread holds rows {wid*16 + g + 8h}, cols j = nt*8 + 2t + e
    float lg[2][OUT_];
    #pragma unroll
    for (int h = 0; h < 2; h++)
        #pragma unroll
        for (int o = 0; o < OUT_; o++) lg[h][o] = 0.f;

    #pragma unroll
    for (int nt = 0; nt < 8; nt++) {
        #pragma unroll
        for (int e = 0; e < 2; e++) {
            const int j = nt * 8 + 2 * t + e;
            const float bias = b1s[j];
            float wv[OUT_];
            #pragma unroll
            for (int o = 0; o < OUT_; o++) wv[o] = w2s[o * HIDDEN_ + j];
            #pragma unroll
            for (int h = 0; h < 2; h++) {
                float hv = fmaxf(acc[nt][h * 2 + e] + bias, 0.f);
                #pragma unroll
                for (int o = 0; o < OUT_; o++)
                    lg[h][o] = fmaf(hv, wv[o], lg[h][o]);
            }
        }
    }
    #pragma unroll
    for (int h = 0; h < 2; h++)
        #pragma unroll
        for (int o = 0; o < OUT_; o++) {
            lg[h][o] += __shfl_xor_sync(0xffffffffu, lg[h][o], 1);
            lg[h][o] += __shfl_xor_sync(0xffffffffu, lg[h][o], 2);
        }

    float ce = 0.f;
    if (t == 0) {
        #pragma unroll
        for (int h = 0; h < 2; h++) {
            const int gn = n0 + wid * 16 + g + 8 * h;
            if (gn < NTEST) {
                float logits[OUT_];
                #pragma unroll
                for (int o = 0; o < OUT_; o++) logits[o] = lg[h][o] + b2s[o];
                float m = logits[0];
                #pragma unroll
                for (int o = 1; o < OUT_; o++) m = fmaxf(m, logits[o]);
                float s = 0.f;
                #pragma unroll
                for (int o = 0; o < OUT_; o++) s += expf(logits[o] - m);
                float lse = m + logf(s);
                int tg = tar2[(size_t)b * NTEST + gn];
                float picked = 0.f;
                #pragma unroll
                for (int o = 0; o < OUT_; o++) picked = (o == tg) ? logits[o] : picked;
                ce += lse - picked;
            }
        }
    }
    #pragma unroll
    for (int off = 16; off; off >>= 1) ce += __shfl_down_sync(0xffffffffu, ce, off);
    if (lane == 0) warpsum[wid] = ce;
    __syncthreads();
    if (tid == 0) {
        float tot = 0.f;
        #pragma unroll
        for (int i = 0; i < 8; i++) tot += warpsum[i];
        atomicAdd(&g_acc2, (double)tot);
    }
}

// ---------------- finalize: reduce loss1 partials + combine ----------------
__global__ __launch_bounds__(256) void fin_k(float* __restrict__ out) {
    __shared__ float ws[8];
    float s = 0.f;
    for (int i = threadIdx.x; i < PREPB; i += 256) s += g_l1part[i];
    #pragma unroll
    for (int off = 16; off; off >>= 1) s += __shfl_down_sync(0xffffffffu, s, off);
    int lane = threadIdx.x & 31, wrp = threadIdx.x >> 5;
    if (lane == 0) ws[wrp] = s;
    __syncthreads();
    if (threadIdx.x == 0) {
        float tot = 0.f;
        #pragma unroll
        for (int i = 0; i < 8; i++) tot += ws[i];
        float l1 = (float)(20.0 * ((double)tot / (double)((size_t)B_ * WVEC)));
        float l2 = (float)(g_acc2 / (double)((size_t)B_ * NTEST));
        out[0] = l1 + l2;
        out[1] = l1;
        out[2] = l2;
    }
}

extern "C" void kernel_launch(void* const* d_in, const int* in_sizes, int n_in,
                              void* d_out, int out_size) {
    const float* inp1   = (const float*)d_in[0];
    const float* tar1   = (const float*)d_in[1];
    const float* inp2   = (const float*)d_in[2];
    const int*   tar2   = (const int*)d_in[3];
    const float* images = (const float*)d_in[4];
    float* out = (float*)d_out;

    prep_k<<<PREPB, 256>>>(images, inp2, inp1, tar1);
    dim3 grid(NTILE_, B_);
    mlp_ce_mma_k<<<grid, 256>>>(inp2, tar2);
    fin_k<<<1, 256>>>(out);
}